// round 17
// baseline (speedup 1.0000x reference)
#include <cuda_runtime.h>
#include <cuda_fp16.h>
#include <cstddef>
#include <cstdint>

// VarConvND: 4096 independent GEMMs [B=64 x K=288] x [K=288 x C_OUT=16].
// fp16 MMA m16n8k16 (fp32 accum): m = C_OUT, n = batch.
// K pipelined: 3 chunks x 96 rows, double-buffered via cp.async.
// Output written directly (scattered STG.32; adjacent-s blocks merge sectors in L2).
//   out[b,c,s] = sum_k u[b,k]*w[k,c] + bias[s]*sum_k w[k,c]

#define S_TOT 4096
#define KK    288
#define CO    16
#define CI    32
#define BB    64
#define HH    64
#define WW    64
#define P_TOT (CI*HH*WW)            // 131072

#define CKR   96                    // k-rows per chunk (6 k16 steps)
#define HST   72                    // X smem row stride in halfs (144 B)
#define WSTW  20                    // W smem row stride in words

#define XB_HALFS (CKR*HST)          // 6912 halfs = 3456 words
#define WB_WORDS (CKR*WSTW)         // 1920 words
#define XB0H  0
#define XB1H  XB_HALFS
#define WB0   (XB_HALFS)            // word offset
#define WB1   (XB_HALFS + WB_WORDS)
#define SMEM_WORDS (XB_HALFS + 2*WB_WORDS)
#define SMEM_BYTES (SMEM_WORDS * 4)          // 43,008 B -> 5 CTAs/SM

__device__ __half g_Xt[(size_t)P_TOT * BB];       // X^T fp16, [p][b]

__device__ __forceinline__ unsigned h2_bits(__half2 h)
{
    return *reinterpret_cast<unsigned*>(&h);
}

// ---------- transpose + fp16-round: X[b][p] fp32 -> Xt[p][b] fp16 ----------
__global__ __launch_bounds__(256)
void transpose_in(const float* __restrict__ X, __half* __restrict__ Xt)
{
    __shared__ float tt[64][65];
    const int tid = threadIdx.x;
    const int p0  = blockIdx.x * 64;

    #pragma unroll
    for (int i = 0; i < 4; i++) {
        const int u = tid + 256 * i;
        const int b = u >> 4;
        const int q = u & 15;
        float4 v = *(const float4*)(X + (size_t)b * P_TOT + p0 + 4 * q);
        tt[4 * q + 0][b] = v.x;
        tt[4 * q + 1][b] = v.y;
        tt[4 * q + 2][b] = v.z;
        tt[4 * q + 3][b] = v.w;
    }
    __syncthreads();
    #pragma unroll
    for (int i = 0; i < 2; i++) {
        const int u = tid + 256 * i;      // 512 units: 64 rows x 8 units of 8 halfs
        const int p = u >> 3;
        const int q = u & 7;
        uint4 o;
        o.x = h2_bits(__floats2half2_rn(tt[p][8 * q + 0], tt[p][8 * q + 1]));
        o.y = h2_bits(__floats2half2_rn(tt[p][8 * q + 2], tt[p][8 * q + 3]));
        o.z = h2_bits(__floats2half2_rn(tt[p][8 * q + 4], tt[p][8 * q + 5]));
        o.w = h2_bits(__floats2half2_rn(tt[p][8 * q + 6], tt[p][8 * q + 7]));
        *(uint4*)(Xt + (size_t)(p0 + p) * BB + 8 * q) = o;
    }
}

// ---------- main kernel ----------
__device__ __forceinline__ void cp16(unsigned dst, const void* src, bool ok)
{
    int sz = ok ? 16 : 0;
    asm volatile("cp.async.cg.shared.global [%0], [%1], 16, %2;\n"
                 :: "r"(dst), "l"(src), "r"(sz) : "memory");
}
#define CP_COMMIT() asm volatile("cp.async.commit_group;\n" ::: "memory")
#define CP_WAIT(N)  asm volatile("cp.async.wait_group %0;\n" :: "n"(N) : "memory")

__global__ __launch_bounds__(128)
void varconv_mma(const float* __restrict__ Wg,
                 const float* __restrict__ bias,
                 float* __restrict__ out)
{
    extern __shared__ float smf[];
    const unsigned smb = (unsigned)__cvta_generic_to_shared(smf);

    const int s    = blockIdx.x;
    const int y    = s >> 6;
    const int x    = s & 63;
    const int tid  = threadIdx.x;
    const int lane = tid & 31;
    const int wid  = tid >> 5;       // warp -> n-block of 16 batches

    const float* wp = Wg + (size_t)s * (KK * CO);

    // ---- stage one W chunk (96 rows x 16 fp32, stride 20 words) ----
    auto stage_w = [&](int chunk, int wbuf) {
        const int q  = tid & 3;           // 16B unit (4 c's)
        const int r0 = tid >> 2;          // 0..31
        #pragma unroll
        for (int j = 0; j < 3; j++) {     // rows r0, r0+32, r0+64
            const int r = r0 + 32 * j;
            cp16(smb + (unsigned)(wbuf + r * WSTW + q * 4) * 4u,
                 wp + (chunk * CKR + r) * CO + q * 4, true);
        }
    };

    // ---- stage one X chunk (96 k-rows x 64 batches fp16, stride 72 halfs) ----
    auto stage_x = [&](int chunk, int xbufh) {
        const int q  = tid & 7;           // 16B unit (8 halfs)
        const int r0 = tid >> 3;          // 0..15
        #pragma unroll
        for (int j = 0; j < 6; j++) {
            const int r   = r0 + 16 * j;  // 0..95
            const int k   = chunk * CKR + r;
            const int cl  = k / 9;
            const int tap = k - cl * 9;
            const int t3  = tap / 3;
            const int yy  = y + t3 - 1;
            const int xx  = x + (tap - 3 * t3) - 1;
            const bool ok = ((unsigned)yy < (unsigned)HH) & ((unsigned)xx < (unsigned)WW);
            const __half* src = ok
                ? g_Xt + ((size_t)((cl << 12) + (yy << 6) + xx) << 6) + q * 8
                : g_Xt;
            cp16(smb + (unsigned)(xbufh + r * HST + q * 8) * 2u, src, ok);
        }
    };

    stage_w(0, WB0);
    stage_x(0, XB0H);
    CP_COMMIT();                          // G0 = W0 + X0
    stage_w(1, WB1);
    stage_x(1, XB1H);
    CP_COMMIT();                          // G1 = W1 + X1

    // fragment roles
    const int cc = lane & 3;
    const int r4 = lane >> 2;
    // ldmatrix B address components (X smem, halfs)
    const int ln_k = (lane & 7) + 8 * ((lane >> 3) & 1);
    const int ln_n = wid * 16 + 8 * (lane >> 4);

    float acc[2][4] = {};
    float cs0 = 0.f, cs1 = 0.f;

    auto compute = [&](int xbufh, int wbuf) {
        #pragma unroll
        for (int i = 0; i < 6; i++) {
            // ---- A from fp32 W smem: 8 LDS.32 + 4 cvt-pack ----
            const int wr = wbuf + (16 * i + 2 * cc) * WSTW;
            const float wa  = smf[wr + r4];
            const float wb_ = smf[wr + WSTW + r4];
            const float wc  = smf[wr + 8 * WSTW + r4];
            const float wd  = smf[wr + 9 * WSTW + r4];
            const float we  = smf[wr + r4 + 8];
            const float wf_ = smf[wr + WSTW + r4 + 8];
            const float wg  = smf[wr + 8 * WSTW + r4 + 8];
            const float wh  = smf[wr + 9 * WSTW + r4 + 8];
            cs0 += (wa + wb_) + (wc + wd);
            cs1 += (we + wf_) + (wg + wh);
            const unsigned a0 = h2_bits(__floats2half2_rn(wa, wb_));
            const unsigned a1 = h2_bits(__floats2half2_rn(we, wf_));
            const unsigned a2 = h2_bits(__floats2half2_rn(wc, wd));
            const unsigned a3 = h2_bits(__floats2half2_rn(wg, wh));

            // ---- B from fp16 X smem via ldmatrix.x4.trans ----
            unsigned b0, b1, b2, b3;
            const unsigned baddr = smb +
                (unsigned)(xbufh + (16 * i + ln_k) * HST + ln_n) * 2u;
            asm volatile(
                "ldmatrix.sync.aligned.m8n8.x4.trans.shared.b16 "
                "{%0,%1,%2,%3}, [%4];"
                : "=r"(b0), "=r"(b1), "=r"(b2), "=r"(b3) : "r"(baddr));

            asm volatile(
                "mma.sync.aligned.m16n8k16.row.col.f32.f16.f16.f32 "
                "{%0,%1,%2,%3}, {%4,%5,%6,%7}, {%8,%9}, {%0,%1,%2,%3};"
                : "+f"(acc[0][0]), "+f"(acc[0][1]), "+f"(acc[0][2]), "+f"(acc[0][3])
                : "r"(a0), "r"(a1), "r"(a2), "r"(a3), "r"(b0), "r"(b1));
            asm volatile(
                "mma.sync.aligned.m16n8k16.row.col.f32.f16.f16.f32 "
                "{%0,%1,%2,%3}, {%4,%5,%6,%7}, {%8,%9}, {%0,%1,%2,%3};"
                : "+f"(acc[1][0]), "+f"(acc[1][1]), "+f"(acc[1][2]), "+f"(acc[1][3])
                : "r"(a0), "r"(a1), "r"(a2), "r"(a3), "r"(b2), "r"(b3));
        }
    };

    CP_WAIT(1); __syncthreads();          // W0 + X0 visible
    compute(XB0H, WB0);
    __syncthreads();                      // buffer-0 readers done
    stage_w(2, WB0); stage_x(2, XB0H); CP_COMMIT();

    CP_WAIT(1); __syncthreads();          // chunk1 visible
    compute(XB1H, WB1);

    CP_WAIT(0); __syncthreads();          // chunk2 visible
    compute(XB0H, WB0);

    // ---- colsum: each warp saw all k x c; reduce over cc lanes ----
    cs0 += __shfl_xor_sync(0xffffffffu, cs0, 1);
    cs0 += __shfl_xor_sync(0xffffffffu, cs0, 2);
    cs1 += __shfl_xor_sync(0xffffffffu, cs1, 1);
    cs1 += __shfl_xor_sync(0xffffffffu, cs1, 2);

    // ---- epilogue: D frag -> out[(b*16+c)*S + s] directly ----
    // Scattered STG.32; blocks with adjacent s merge into the same L2 sectors.
    {
        const float bval = bias[s];
        const float bt0 = bval * cs0;     // c = r4
        const float bt1 = bval * cs1;     // c = r4 + 8
        #pragma unroll
        for (int nt = 0; nt < 2; nt++) {
            const int nb = wid * 16 + 8 * nt + 2 * cc;   // batch pair nb, nb+1
            out[((size_t)(nb       * CO + r4)     ) * S_TOT + s] = acc[nt][0] + bt0;
            out[((size_t)((nb + 1) * CO + r4)     ) * S_TOT + s] = acc[nt][1] + bt0;
            out[((size_t)(nb       * CO + r4 + 8) ) * S_TOT + s] = acc[nt][2] + bt1;
            out[((size_t)((nb + 1) * CO + r4 + 8) ) * S_TOT + s] = acc[nt][3] + bt1;
        }
    }
}

extern "C" void kernel_launch(void* const* d_in, const int* in_sizes, int n_in,
                              void* d_out, int out_size)
{
    const float* X    = (const float*)d_in[0];
    const float* Wg   = (const float*)d_in[1];
    const float* bias = (const float*)d_in[2];
    float* out        = (float*)d_out;
    (void)in_sizes; (void)n_in; (void)out_size;

    __half* Xt = nullptr;
    cudaGetSymbolAddress((void**)&Xt, g_Xt);

    cudaFuncSetAttribute(varconv_mma,
                         cudaFuncAttributeMaxDynamicSharedMemorySize, SMEM_BYTES);

    transpose_in<<<P_TOT / 64, 256>>>(X, Xt);

    varconv_mma<<<S_TOT, 128, SMEM_BYTES>>>(Wg, bias, out);
}